// round 16
// baseline (speedup 1.0000x reference)
#include <cuda_runtime.h>
#include <cuda_bf16.h>
#include <cstdint>

#define T_SEQ   2049
#define D_MODEL 1024
#define NHEAD   16
#define HDIM    64
#define KDIM    1024

// ===========================================================================
// Scratch (static __device__ — no allocation anywhere, per harness rules)
// ===========================================================================
__device__ float g_qh[(size_t)NHEAD * T_SEQ * HDIM];
__device__ float g_kh[(size_t)NHEAD * T_SEQ * HDIM];
__device__ float g_vh[(size_t)NHEAD * T_SEQ * HDIM];
__device__ float g_S [(size_t)NHEAD * T_SEQ * T_SEQ];
__device__ float g_ctx[(size_t)T_SEQ * D_MODEL];

// ===========================================================================
// Warp MMA helpers (baseline PTX — works on compute_103 non-'a' target)
// ===========================================================================
__device__ __forceinline__ uint32_t smem_u32(const void* p) {
    uint32_t a;
    asm("{ .reg .u64 t; cvta.to.shared.u64 t, %1; cvt.u32.u64 %0, t; }"
        : "=r"(a) : "l"(p));
    return a;
}

__device__ __forceinline__ void ldsm4(uint32_t r[4], uint32_t addr) {
    asm volatile("ldmatrix.sync.aligned.m8n8.x4.shared.b16 {%0,%1,%2,%3}, [%4];"
                 : "=r"(r[0]), "=r"(r[1]), "=r"(r[2]), "=r"(r[3]) : "r"(addr));
}

__device__ __forceinline__ void mma16816(float c[4], const uint32_t a[4],
                                         uint32_t b0, uint32_t b1) {
    asm volatile(
        "mma.sync.aligned.m16n8k16.row.col.f32.bf16.bf16.f32 "
        "{%0,%1,%2,%3}, {%4,%5,%6,%7}, {%8,%9}, {%0,%1,%2,%3};"
        : "+f"(c[0]), "+f"(c[1]), "+f"(c[2]), "+f"(c[3])
        : "r"(a[0]), "r"(a[1]), "r"(a[2]), "r"(a[3]), "r"(b0), "r"(b1));
}

__device__ __forceinline__ uint32_t bpack(__nv_bfloat16 a, __nv_bfloat16 b) {
    __nv_bfloat162 t; t.x = a; t.y = b;
    return *(uint32_t*)&t;
}

// ===========================================================================
// HMMA 3x-bf16 NT GEMM: C[m,n] = sum_k A[m,k]*W[n,k] + bias[n]  (fp32 in/out)
// fp32 loads are split to (hi,lo) bf16 in registers; K' = 3K passes:
// Ah*Bh + Al*Bh + Ah*Bl (error ~2^-16).
// CTA 128x128, 8 warps (2m x 4n), warp 64x32, K-slab 32, double-buffered.
// SCATTER=1 -> head-major (H,T,HD); SCATTER=0 -> row-major (T,D).
// ===========================================================================
#define PLANE   10240                        // 128 rows * 80 B (40 bf16, padded)
#define GEMM_MMA_SMEM (2 * 4 * PLANE)        // 81920 B

template<int SCATTER>
__global__ __launch_bounds__(256)
void gemm_mma(const float* __restrict__ A, const float* __restrict__ W,
              const float* __restrict__ bias, float* __restrict__ out) {
    extern __shared__ char smem[];
    const int M = T_SEQ, K = KDIM;
    const int m0 = blockIdx.y * 128;
    const int n0 = blockIdx.x * 128;
    const int tid  = threadIdx.x;
    const int lane = tid & 31;
    const int wid  = tid >> 5;
    const int wm   = wid >> 2;               // 0..1  (64-row warp tile)
    const int wn   = wid & 3;                // 0..3  (32-col warp tile)

    // plane base byte offsets: [buf][Ah,Al,Bh,Bl]
    auto plane = [&](int buf, int p) { return (buf * 4 + p) * PLANE; };

    const int lrow = tid >> 1;               // 0..127
    const int lcb  = (tid & 1) * 16;         // 0 or 16 (fp32 col base)
    const bool aok = (m0 + lrow) < M;
    const float* aptr = A + (size_t)(m0 + lrow) * K + lcb;
    const float* wptr = W + (size_t)(n0 + lrow) * K + lcb;

    float fa[16], fb[16];

#define LDG_SLAB(s) do {                                                      \
    const int _k0 = (s) * 32;                                                 \
    _Pragma("unroll")                                                         \
    for (int c = 0; c < 4; c++) {                                             \
        float4 va = aok ? *(const float4*)(aptr + _k0 + c * 4)                \
                        : make_float4(0.f, 0.f, 0.f, 0.f);                    \
        float4 vb = *(const float4*)(wptr + _k0 + c * 4);                     \
        fa[c*4+0] = va.x; fa[c*4+1] = va.y; fa[c*4+2] = va.z; fa[c*4+3] = va.w; \
        fb[c*4+0] = vb.x; fb[c*4+1] = vb.y; fb[c*4+2] = vb.z; fb[c*4+3] = vb.w; \
    }                                                                         \
} while (0)

#define STS_SLAB(buf) do {                                                    \
    uint32_t hiA[8], loA[8], hiB[8], loB[8];                                  \
    _Pragma("unroll")                                                         \
    for (int c = 0; c < 8; c++) {                                             \
        float x = fa[c*2], y = fa[c*2+1];                                     \
        __nv_bfloat16 hx = __float2bfloat16(x), hy = __float2bfloat16(y);     \
        hiA[c] = bpack(hx, hy);                                               \
        loA[c] = bpack(__float2bfloat16(x - __bfloat162float(hx)),            \
                       __float2bfloat16(y - __bfloat162float(hy)));           \
        x = fb[c*2]; y = fb[c*2+1];                                           \
        hx = __float2bfloat16(x); hy = __float2bfloat16(y);                   \
        hiB[c] = bpack(hx, hy);                                               \
        loB[c] = bpack(__float2bfloat16(x - __bfloat162float(hx)),            \
                       __float2bfloat16(y - __bfloat162float(hy)));           \
    }                                                                         \
    const uint32_t so = (uint32_t)lrow * 80u + (uint32_t)lcb * 2u;            \
    *(uint4*)(smem + plane(buf,0) + so)      = *(uint4*)(hiA);                \
    *(uint4*)(smem + plane(buf,0) + so + 16) = *(uint4*)(hiA + 4);            \
    *(uint4*)(smem + plane(buf,1) + so)      = *(uint4*)(loA);                \
    *(uint4*)(smem + plane(buf,1) + so + 16) = *(uint4*)(loA + 4);            \
    *(uint4*)(smem + plane(buf,2) + so)      = *(uint4*)(hiB);                \
    *(uint4*)(smem + plane(buf,2) + so + 16) = *(uint4*)(hiB + 4);            \
    *(uint4*)(smem + plane(buf,3) + so)      = *(uint4*)(loB);                \
    *(uint4*)(smem + plane(buf,3) + so + 16) = *(uint4*)(loB + 4);            \
} while (0)

    float acc[4][4][4] = {};
    const uint32_t sb = smem_u32(smem);
    // ldmatrix per-lane address components
    const uint32_t aRow = (uint32_t)(wm * 64 + (lane & 15)) * 80u + ((lane >> 4) << 4);
    const uint32_t bRow = (uint32_t)(wn * 32 + (lane & 7) + ((lane >> 4) << 3)) * 80u
                        + (((lane >> 3) & 1) << 4);

    LDG_SLAB(0);
    STS_SLAB(0);
    __syncthreads();

    for (int s = 0; s < 32; s++) {
        const int b = s & 1;
        if (s + 1 < 32) LDG_SLAB(s + 1);

        const uint32_t pA[3] = { sb + plane(b,0), sb + plane(b,1), sb + plane(b,0) };
        const uint32_t pB[3] = { sb + plane(b,2), sb + plane(b,2), sb + plane(b,3) };
#pragma unroll
        for (int ks = 0; ks < 2; ks++) {
            const uint32_t kb = ks * 32;     // 16 bf16 = 32 bytes
#pragma unroll
            for (int p = 0; p < 3; p++) {
                uint32_t af[4][4];
#pragma unroll
                for (int mi = 0; mi < 4; mi++)
                    ldsm4(af[mi], pA[p] + aRow + (uint32_t)(mi * 16) * 80u + kb);
                uint32_t bf4[2][4];
#pragma unroll
                for (int nb = 0; nb < 2; nb++)
                    ldsm4(bf4[nb], pB[p] + bRow + (uint32_t)(nb * 16) * 80u + kb);
#pragma unroll
                for (int mi = 0; mi < 4; mi++)
#pragma unroll
                    for (int ni = 0; ni < 4; ni++)
                        mma16816(acc[mi][ni], af[mi],
                                 bf4[ni >> 1][(ni & 1) * 2],
                                 bf4[ni >> 1][(ni & 1) * 2 + 1]);
            }
        }

        if (s + 1 < 32) {
            __syncthreads();
            STS_SLAB(b ^ 1);
            __syncthreads();
        }
    }

    // Epilogue: c-frag {c0,c1}@(row, col..col+1), {c2,c3}@(row+8, ...)
    const int rbase = m0 + wm * 64 + (lane >> 2);
    const int cbase = n0 + wn * 32 + (lane & 3) * 2;
#pragma unroll
    for (int mi = 0; mi < 4; mi++) {
#pragma unroll
        for (int half = 0; half < 2; half++) {
            const int m = rbase + mi * 16 + half * 8;
            if (m >= M) continue;
#pragma unroll
            for (int ni = 0; ni < 4; ni++) {
                const int n = cbase + ni * 8;
                float2 o;
                o.x = acc[mi][ni][half * 2 + 0] + bias[n];
                o.y = acc[mi][ni][half * 2 + 1] + bias[n + 1];
                if (SCATTER)
                    *(float2*)(out + ((size_t)(n >> 6) * M + m) * HDIM + (n & 63)) = o;
                else
                    *(float2*)(out + (size_t)m * D_MODEL + n) = o;
            }
        }
    }
#undef LDG_SLAB
#undef STS_SLAB
}

// ===========================================================================
// Scores: S[h,t,s] = ( qh[h,t]·kh[h,s] + qh[h,t+1]·Er[s] ) * 0.125
// (SIMT fp32, 128x128 tile — measured 254us in R11)
// ===========================================================================
__global__ __launch_bounds__(256)
void scores128(const float* __restrict__ qh, const float* __restrict__ kh,
               const float* __restrict__ Er, float* __restrict__ S) {
    const int m0 = blockIdx.y * 128;
    const int n0 = blockIdx.x * 128;
    if (n0 > m0 + 127) return;
    const int h = blockIdx.z;
    const int T = T_SEQ;

    __shared__ float As[8][132];
    __shared__ float Bs[8][132];
    const int tid = threadIdx.x;
    const int tx = tid & 15, ty = tid >> 4;
    const int lrow = tid >> 1;
    const int lk   = (tid & 1) * 4;

    const float* qbase = qh + (size_t)h * T * HDIM;
    const float* kbase = kh + (size_t)h * T * HDIM;
    float acc[8][8] = {};

    for (int k0 = 0; k0 < 128; k0 += 8) {
        const int kq = k0 + lk;
        float4 va = make_float4(0.f, 0.f, 0.f, 0.f);
        {
            int t = m0 + lrow;
            if (kq < 64) {
                if (t < T) va = *(const float4*)(qbase + (size_t)t * HDIM + kq);
            } else {
                int t2 = t + 1;
                if (t2 < T) va = *(const float4*)(qbase + (size_t)t2 * HDIM + (kq - 64));
            }
        }
        float4 vb = make_float4(0.f, 0.f, 0.f, 0.f);
        {
            int s = n0 + lrow;
            if (s < T) {
                if (kq < 64) vb = *(const float4*)(kbase + (size_t)s * HDIM + kq);
                else         vb = *(const float4*)(Er + (size_t)s * HDIM + (kq - 64));
            }
        }
        As[lk+0][lrow] = va.x; As[lk+1][lrow] = va.y;
        As[lk+2][lrow] = va.z; As[lk+3][lrow] = va.w;
        Bs[lk+0][lrow] = vb.x; Bs[lk+1][lrow] = vb.y;
        Bs[lk+2][lrow] = vb.z; Bs[lk+3][lrow] = vb.w;
        __syncthreads();
#pragma unroll
        for (int kk = 0; kk < 8; kk++) {
            float a[8], b[8];
            *(float4*)(a)     = *(const float4*)&As[kk][ty * 4];
            *(float4*)(a + 4) = *(const float4*)&As[kk][64 + ty * 4];
            *(float4*)(b)     = *(const float4*)&Bs[kk][tx * 4];
            *(float4*)(b + 4) = *(const float4*)&Bs[kk][64 + tx * 4];
#pragma unroll
            for (int i = 0; i < 8; i++)
#pragma unroll
                for (int j = 0; j < 8; j++)
                    acc[i][j] = fmaf(a[i], b[j], acc[i][j]);
        }
        __syncthreads();
    }

    float* sbase = S + (size_t)h * T * T;
#pragma unroll
    for (int i = 0; i < 8; i++) {
        int t = m0 + ((i < 4) ? (ty * 4 + i) : (64 + ty * 4 + i - 4));
        if (t >= T) continue;
#pragma unroll
        for (int j = 0; j < 8; j++) {
            int s = n0 + ((j < 4) ? (tx * 4 + j) : (64 + tx * 4 + j - 4));
            if (s < T) sbase[(size_t)t * T + s] = acc[i][j] * 0.125f;
        }
    }
}

// ===========================================================================
// Row softmax over s in [0, t], in place; zero-fill to 128-aligned boundary.
// ===========================================================================
__global__ __launch_bounds__(256)
void softmax_kernel(float* __restrict__ S) {
    const int T = T_SEQ;
    const int t = blockIdx.x;
    const int h = blockIdx.y;
    float* r = S + ((size_t)h * T + t) * T;
    const int tid = threadIdx.x;
    __shared__ float red[32];

    float m = -1e30f;
    for (int s = tid; s <= t; s += 256) m = fmaxf(m, r[s]);
#pragma unroll
    for (int o = 16; o; o >>= 1) m = fmaxf(m, __shfl_xor_sync(~0u, m, o));
    if ((tid & 31) == 0) red[tid >> 5] = m;
    __syncthreads();
    if (tid < 32) {
        float v = (tid < 8) ? red[tid] : -1e30f;
#pragma unroll
        for (int o = 4; o; o >>= 1) v = fmaxf(v, __shfl_xor_sync(~0u, v, o));
        if (tid == 0) red[0] = v;
    }
    __syncthreads();
    m = red[0];
    __syncthreads();

    float sum = 0.f;
    for (int s = tid; s <= t; s += 256) {
        float e = __expf(r[s] - m);
        r[s] = e;
        sum += e;
    }
#pragma unroll
    for (int o = 16; o; o >>= 1) sum += __shfl_xor_sync(~0u, sum, o);
    if ((tid & 31) == 0) red[tid >> 5] = sum;
    __syncthreads();
    if (tid < 32) {
        float v = (tid < 8) ? red[tid] : 0.f;
#pragma unroll
        for (int o = 4; o; o >>= 1) v += __shfl_xor_sync(~0u, v, o);
        if (tid == 0) red[0] = v;
    }
    __syncthreads();
    const float inv = 1.0f / red[0];
    const int bound = min((((t >> 7) + 1) << 7), T);
    for (int s = tid; s < bound; s += 256)
        r[s] = (s <= t) ? r[s] * inv : 0.0f;
}

// ===========================================================================
// AV: ctx[t, h*64+d] = sum_{s<=t} P[h,t,s] * vh[h,s,d]
// (64x64 tile version — R10 config, better occupancy)
// ===========================================================================
__global__ __launch_bounds__(256)
void av_kernel(const float* __restrict__ S, const float* __restrict__ vh,
               float* __restrict__ ctx) {
    const int T = T_SEQ;
    const int m0 = blockIdx.x * 64;
    const int h  = blockIdx.y;
    const int tid = threadIdx.x;
    const int tx = tid & 15, ty = tid >> 4;

    __shared__ float Ps[16][68];
    __shared__ float Vs[16][68];
    float acc[4][4] = {};

    const float* sbase = S  + (size_t)h * T * T;
    const float* vbase = vh + (size_t)h * T * HDIM;
    const int smax = min(m0 + 63, T - 1);

    const int prow = tid >> 2;
    const int pss  = (tid & 3) * 4;
    const int vsr  = tid >> 4;
    const int vd4  = (tid & 15) * 4;

    for (int s0 = 0; s0 <= smax; s0 += 16) {
        {
            int t = m0 + prow;
#pragma unroll
            for (int i = 0; i < 4; i++) {
                int s = s0 + pss + i;
                float v = 0.f;
                if (t < T && s < T) v = sbase[(size_t)t * T + s];
                Ps[pss + i][prow] = v;
            }
        }
        {
            int s = s0 + vsr;
            float4 vv = make_float4(0.f, 0.f, 0.f, 0.f);
            if (s < T) vv = *(const float4*)(vbase + (size_t)s * HDIM + vd4);
            Vs[vsr][vd4+0] = vv.x; Vs[vsr][vd4+1] = vv.y;
            Vs[vsr][vd4+2] = vv.z; Vs[vsr][vd4+3] = vv.w;
        }
        __syncthreads();
#pragma unroll
        for (int kk = 0; kk < 16; kk++) {
            float4 a4 = *(const float4*)&Ps[kk][ty * 4];
            float4 b4 = *(const float4*)&Vs[kk][tx * 4];
            float a[4] = {a4.x, a4.y, a4.z, a4.w};
            float b[4] = {b4.x, b4.y, b4.z, b4.w};
#pragma unroll
            for (int i = 0; i < 4; i++)
#pragma unroll
                for (int j = 0; j < 4; j++)
                    acc[i][j] = fmaf(a[i], b[j], acc[i][j]);
        }
        __syncthreads();
    }

#pragma unroll
    for (int i = 0; i < 4; i++) {
        int t = m0 + ty * 4 + i;
        if (t >= T) continue;
#pragma unroll
        for (int j = 0; j < 4; j++) {
            int d = tx * 4 + j;
            ctx[(size_t)t * D_MODEL + h * HDIM + d] = acc[i][j];
        }
    }
}

// ===========================================================================
// Launch. Inputs: q,k,v,mask,Wq_w,Wq_b,Wk_w,Wk_b,Wv_w,Wv_b,Er,Wo_w,Wo_b.
// ===========================================================================
extern "C" void kernel_launch(void* const* d_in, const int* in_sizes, int n_in,
                              void* d_out, int out_size) {
    const float* q    = (const float*)d_in[0];
    const float* k    = (const float*)d_in[1];
    const float* v    = (const float*)d_in[2];
    const float* Wq_w = (const float*)d_in[4];
    const float* Wq_b = (const float*)d_in[5];
    const float* Wk_w = (const float*)d_in[6];
    const float* Wk_b = (const float*)d_in[7];
    const float* Wv_w = (const float*)d_in[8];
    const float* Wv_b = (const float*)d_in[9];
    const float* Er   = (const float*)d_in[10];
    const float* Wo_w = (const float*)d_in[11];
    const float* Wo_b = (const float*)d_in[12];
    float* out = (float*)d_out;

    float *qh, *kh, *vh, *S, *ctx;
    cudaGetSymbolAddress((void**)&qh,  g_qh);
    cudaGetSymbolAddress((void**)&kh,  g_kh);
    cudaGetSymbolAddress((void**)&vh,  g_vh);
    cudaGetSymbolAddress((void**)&S,   g_S);
    cudaGetSymbolAddress((void**)&ctx, g_ctx);

    cudaFuncSetAttribute(gemm_mma<1>, cudaFuncAttributeMaxDynamicSharedMemorySize, GEMM_MMA_SMEM);
    cudaFuncSetAttribute(gemm_mma<0>, cudaFuncAttributeMaxDynamicSharedMemorySize, GEMM_MMA_SMEM);

    const int mt = (T_SEQ + 127) / 128;          // 17
    dim3 gG(D_MODEL / 128, mt);                  // (8, 17)

    gemm_mma<1><<<gG, 256, GEMM_MMA_SMEM>>>(q, Wq_w, Wq_b, qh);
    gemm_mma<1><<<gG, 256, GEMM_MMA_SMEM>>>(k, Wk_w, Wk_b, kh);
    gemm_mma<1><<<gG, 256, GEMM_MMA_SMEM>>>(v, Wv_w, Wv_b, vh);

    dim3 blk(256);
    dim3 gS(mt, mt, NHEAD);
    scores128<<<gS, blk>>>(qh, kh, Er, S);

    dim3 gSm(T_SEQ, NHEAD);
    softmax_kernel<<<gSm, blk>>>(S);

    dim3 gAV((T_SEQ + 63) / 64, NHEAD);          // (33, 16)
    av_kernel<<<gAV, blk>>>(S, vh, ctx);

    gemm_mma<0><<<gG, 256, GEMM_MMA_SMEM>>>(ctx, Wo_w, Wo_b, out);
}

// round 17
// speedup vs baseline: 1.1852x; 1.1852x over previous
#include <cuda_runtime.h>
#include <cuda_bf16.h>
#include <cstdint>

#define T_SEQ   2049
#define D_MODEL 1024
#define NHEAD   16
#define HDIM    64
#define KDIM    1024

// ===========================================================================
// Scratch (static __device__ — no allocation anywhere, per harness rules)
// ===========================================================================
__device__ float g_qh[(size_t)NHEAD * T_SEQ * HDIM];
__device__ float g_kh[(size_t)NHEAD * T_SEQ * HDIM];
__device__ float g_vh[(size_t)NHEAD * T_SEQ * HDIM];
__device__ float g_S [(size_t)NHEAD * T_SEQ * T_SEQ];
__device__ float g_ctx[(size_t)T_SEQ * D_MODEL];

// ===========================================================================
// Warp MMA helpers (baseline PTX — works on compute_103 non-'a' target)
// ===========================================================================
__device__ __forceinline__ uint32_t smem_u32(const void* p) {
    uint32_t a;
    asm("{ .reg .u64 t; cvta.to.shared.u64 t, %1; cvt.u32.u64 %0, t; }"
        : "=r"(a) : "l"(p));
    return a;
}

__device__ __forceinline__ void ldsm4(uint32_t r[4], uint32_t addr) {
    asm volatile("ldmatrix.sync.aligned.m8n8.x4.shared.b16 {%0,%1,%2,%3}, [%4];"
                 : "=r"(r[0]), "=r"(r[1]), "=r"(r[2]), "=r"(r[3]) : "r"(addr));
}

__device__ __forceinline__ void mma16816(float c[4], const uint32_t a[4],
                                         uint32_t b0, uint32_t b1) {
    asm volatile(
        "mma.sync.aligned.m16n8k16.row.col.f32.bf16.bf16.f32 "
        "{%0,%1,%2,%3}, {%4,%5,%6,%7}, {%8,%9}, {%0,%1,%2,%3};"
        : "+f"(c[0]), "+f"(c[1]), "+f"(c[2]), "+f"(c[3])
        : "r"(a[0]), "r"(a[1]), "r"(a[2]), "r"(a[3]), "r"(b0), "r"(b1));
}

__device__ __forceinline__ uint32_t bpack(__nv_bfloat16 a, __nv_bfloat16 b) {
    __nv_bfloat162 t; t.x = a; t.y = b;
    return *(uint32_t*)&t;
}

#define PLANE   10240                        // 128 rows * 80 B (32 bf16 + pad)
#define MMA_SMEM (2 * 4 * PLANE)             // 81920 B

// ===========================================================================
// HMMA 3x-bf16 NT GEMM: C[m,n] = sum_k A[m,k]*W[n,k] + bias[n]  (fp32 in/out)
// CTA 128x128, 8 warps (2m x 4n), warp 64x32, K-slab 32, double-buffered.
// SCATTER=1 -> head-major (H,T,HD); SCATTER=0 -> row-major (T,D).
// ===========================================================================
template<int SCATTER>
__global__ __launch_bounds__(256)
void gemm_mma(const float* __restrict__ A, const float* __restrict__ W,
              const float* __restrict__ bias, float* __restrict__ out) {
    extern __shared__ char smem[];
    const int M = T_SEQ, K = KDIM;
    const int m0 = blockIdx.y * 128;
    const int n0 = blockIdx.x * 128;
    const int tid  = threadIdx.x;
    const int lane = tid & 31;
    const int wid  = tid >> 5;
    const int wm   = wid >> 2;
    const int wn   = wid & 3;

    auto plane = [&](int buf, int p) { return (buf * 4 + p) * PLANE; };

    const int lrow = tid >> 1;
    const int lcb  = (tid & 1) * 16;
    const bool aok = (m0 + lrow) < M;
    const float* aptr = A + (size_t)(m0 + lrow) * K + lcb;
    const float* wptr = W + (size_t)(n0 + lrow) * K + lcb;

    float fa[16], fb[16];

#define LDG_SLAB(s) do {                                                      \
    const int _k0 = (s) * 32;                                                 \
    _Pragma("unroll")                                                         \
    for (int c = 0; c < 4; c++) {                                             \
        float4 va = aok ? *(const float4*)(aptr + _k0 + c * 4)                \
                        : make_float4(0.f, 0.f, 0.f, 0.f);                    \
        float4 vb = *(const float4*)(wptr + _k0 + c * 4);                     \
        fa[c*4+0] = va.x; fa[c*4+1] = va.y; fa[c*4+2] = va.z; fa[c*4+3] = va.w; \
        fb[c*4+0] = vb.x; fb[c*4+1] = vb.y; fb[c*4+2] = vb.z; fb[c*4+3] = vb.w; \
    }                                                                         \
} while (0)

#define STS_SLAB(buf) do {                                                    \
    uint32_t hiA[8], loA[8], hiB[8], loB[8];                                  \
    _Pragma("unroll")                                                         \
    for (int c = 0; c < 8; c++) {                                             \
        float x = fa[c*2], y = fa[c*2+1];                                     \
        __nv_bfloat16 hx = __float2bfloat16(x), hy = __float2bfloat16(y);     \
        hiA[c] = bpack(hx, hy);                                               \
        loA[c] = bpack(__float2bfloat16(x - __bfloat162float(hx)),            \
                       __float2bfloat16(y - __bfloat162float(hy)));           \
        x = fb[c*2]; y = fb[c*2+1];                                           \
        hx = __float2bfloat16(x); hy = __float2bfloat16(y);                   \
        hiB[c] = bpack(hx, hy);                                               \
        loB[c] = bpack(__float2bfloat16(x - __bfloat162float(hx)),            \
                       __float2bfloat16(y - __bfloat162float(hy)));           \
    }                                                                         \
    const uint32_t so = (uint32_t)lrow * 80u + (uint32_t)lcb * 2u;            \
    *(uint4*)(smem + plane(buf,0) + so)      = *(uint4*)(hiA);                \
    *(uint4*)(smem + plane(buf,0) + so + 16) = *(uint4*)(hiA + 4);            \
    *(uint4*)(smem + plane(buf,1) + so)      = *(uint4*)(loA);                \
    *(uint4*)(smem + plane(buf,1) + so + 16) = *(uint4*)(loA + 4);            \
    *(uint4*)(smem + plane(buf,2) + so)      = *(uint4*)(hiB);                \
    *(uint4*)(smem + plane(buf,2) + so + 16) = *(uint4*)(hiB + 4);            \
    *(uint4*)(smem + plane(buf,3) + so)      = *(uint4*)(loB);                \
    *(uint4*)(smem + plane(buf,3) + so + 16) = *(uint4*)(loB + 4);            \
} while (0)

    float acc[4][4][4] = {};
    const uint32_t sb = smem_u32(smem);
    const uint32_t aRow = (uint32_t)(wm * 64 + (lane & 15)) * 80u + ((lane >> 4) << 4);
    const uint32_t bRow = (uint32_t)(wn * 32 + (lane & 7) + ((lane >> 4) << 3)) * 80u
                        + (((lane >> 3) & 1) << 4);

    LDG_SLAB(0);
    STS_SLAB(0);
    __syncthreads();

    for (int s = 0; s < 32; s++) {
        const int b = s & 1;
        if (s + 1 < 32) LDG_SLAB(s + 1);

        const uint32_t pA[3] = { sb + plane(b,0), sb + plane(b,1), sb + plane(b,0) };
        const uint32_t pB[3] = { sb + plane(b,2), sb + plane(b,2), sb + plane(b,3) };
#pragma unroll
        for (int ks = 0; ks < 2; ks++) {
            const uint32_t kb = ks * 32;
#pragma unroll
            for (int p = 0; p < 3; p++) {
                uint32_t af[4][4];
#pragma unroll
                for (int mi = 0; mi < 4; mi++)
                    ldsm4(af[mi], pA[p] + aRow + (uint32_t)(mi * 16) * 80u + kb);
                uint32_t bf4[2][4];
#pragma unroll
                for (int nb = 0; nb < 2; nb++)
                    ldsm4(bf4[nb], pB[p] + bRow + (uint32_t)(nb * 16) * 80u + kb);
#pragma unroll
                for (int mi = 0; mi < 4; mi++)
#pragma unroll
                    for (int ni = 0; ni < 4; ni++)
                        mma16816(acc[mi][ni], af[mi],
                                 bf4[ni >> 1][(ni & 1) * 2],
                                 bf4[ni >> 1][(ni & 1) * 2 + 1]);
            }
        }

        if (s + 1 < 32) {
            __syncthreads();
            STS_SLAB(b ^ 1);
            __syncthreads();
        }
    }

    const int rbase = m0 + wm * 64 + (lane >> 2);
    const int cbase = n0 + wn * 32 + (lane & 3) * 2;
#pragma unroll
    for (int mi = 0; mi < 4; mi++) {
#pragma unroll
        for (int half = 0; half < 2; half++) {
            const int m = rbase + mi * 16 + half * 8;
            if (m >= M) continue;
#pragma unroll
            for (int ni = 0; ni < 4; ni++) {
                const int n = cbase + ni * 8;
                float2 o;
                o.x = acc[mi][ni][half * 2 + 0] + bias[n];
                o.y = acc[mi][ni][half * 2 + 1] + bias[n + 1];
                if (SCATTER)
                    *(float2*)(out + ((size_t)(n >> 6) * M + m) * HDIM + (n & 63)) = o;
                else
                    *(float2*)(out + (size_t)m * D_MODEL + n) = o;
            }
        }
    }
#undef LDG_SLAB
#undef STS_SLAB
}

// ===========================================================================
// HMMA 3x-bf16 scores: S[h,t,s] = ([qh[t]|qh[t+1]]·[kh[s]|Er[s]]) * 0.125
// Same machinery as gemm_mma; K=128 augmented = 4 K-slabs of 32.
// Slabs 0,1 = first half (qh[t], kh[s]); slabs 2,3 = second half
// (qh[t+1], Er[s]). Causal tiles above the diagonal skipped.
// ===========================================================================
__global__ __launch_bounds__(256)
void scores_mma(const float* __restrict__ qh, const float* __restrict__ kh,
                const float* __restrict__ Er, float* __restrict__ S) {
    const int m0 = blockIdx.y * 128;
    const int n0 = blockIdx.x * 128;
    if (n0 > m0 + 127) return;
    const int h = blockIdx.z;
    const int T = T_SEQ;

    extern __shared__ char smem[];
    const int tid  = threadIdx.x;
    const int lane = tid & 31;
    const int wid  = tid >> 5;
    const int wm   = wid >> 2;
    const int wn   = wid & 3;

    auto plane = [&](int buf, int p) { return (buf * 4 + p) * PLANE; };

    const int lrow = tid >> 1;
    const int lcb  = (tid & 1) * 16;
    const int tA   = m0 + lrow;          // A row (t)
    const int sB   = n0 + lrow;          // B row (s)

    const float* qbase = qh + (size_t)h * T * HDIM;
    const float* kbase = kh + (size_t)h * T * HDIM;

    float fa[16], fb[16];

#define LDG_SLAB_S(s) do {                                                    \
    const int _kk = ((s) & 1) * 32 + lcb;                                     \
    const float* _ap; bool _aok;                                              \
    if ((s) < 2) { _ap = qbase + (size_t)tA * HDIM;       _aok = tA < T; }    \
    else         { _ap = qbase + (size_t)(tA + 1) * HDIM; _aok = (tA + 1) < T; } \
    const float* _bp; const bool _bok = sB < T;                               \
    if ((s) < 2) _bp = kbase + (size_t)sB * HDIM;                             \
    else         _bp = Er + (size_t)sB * HDIM;                                \
    _Pragma("unroll")                                                         \
    for (int c = 0; c < 4; c++) {                                             \
        float4 va = _aok ? *(const float4*)(_ap + _kk + c * 4)                \
                         : make_float4(0.f, 0.f, 0.f, 0.f);                   \
        float4 vb = _bok ? *(const float4*)(_bp + _kk + c * 4)                \
                         : make_float4(0.f, 0.f, 0.f, 0.f);                   \
        fa[c*4+0] = va.x; fa[c*4+1] = va.y; fa[c*4+2] = va.z; fa[c*4+3] = va.w; \
        fb[c*4+0] = vb.x; fb[c*4+1] = vb.y; fb[c*4+2] = vb.z; fb[c*4+3] = vb.w; \
    }                                                                         \
} while (0)

#define STS_SLAB_S(buf) do {                                                  \
    uint32_t hiA[8], loA[8], hiB[8], loB[8];                                  \
    _Pragma("unroll")                                                         \
    for (int c = 0; c < 8; c++) {                                             \
        float x = fa[c*2], y = fa[c*2+1];                                     \
        __nv_bfloat16 hx = __float2bfloat16(x), hy = __float2bfloat16(y);     \
        hiA[c] = bpack(hx, hy);                                               \
        loA[c] = bpack(__float2bfloat16(x - __bfloat162float(hx)),            \
                       __float2bfloat16(y - __bfloat162float(hy)));           \
        x = fb[c*2]; y = fb[c*2+1];                                           \
        hx = __float2bfloat16(x); hy = __float2bfloat16(y);                   \
        hiB[c] = bpack(hx, hy);                                               \
        loB[c] = bpack(__float2bfloat16(x - __bfloat162float(hx)),            \
                       __float2bfloat16(y - __bfloat162float(hy)));           \
    }                                                                         \
    const uint32_t so = (uint32_t)lrow * 80u + (uint32_t)lcb * 2u;            \
    *(uint4*)(smem + plane(buf,0) + so)      = *(uint4*)(hiA);                \
    *(uint4*)(smem + plane(buf,0) + so + 16) = *(uint4*)(hiA + 4);            \
    *(uint4*)(smem + plane(buf,1) + so)      = *(uint4*)(loA);                \
    *(uint4*)(smem + plane(buf,1) + so + 16) = *(uint4*)(loA + 4);            \
    *(uint4*)(smem + plane(buf,2) + so)      = *(uint4*)(hiB);                \
    *(uint4*)(smem + plane(buf,2) + so + 16) = *(uint4*)(hiB + 4);            \
    *(uint4*)(smem + plane(buf,3) + so)      = *(uint4*)(loB);                \
    *(uint4*)(smem + plane(buf,3) + so + 16) = *(uint4*)(loB + 4);            \
} while (0)

    float acc[4][4][4] = {};
    const uint32_t sb = smem_u32(smem);
    const uint32_t aRow = (uint32_t)(wm * 64 + (lane & 15)) * 80u + ((lane >> 4) << 4);
    const uint32_t bRow = (uint32_t)(wn * 32 + (lane & 7) + ((lane >> 4) << 3)) * 80u
                        + (((lane >> 3) & 1) << 4);

    LDG_SLAB_S(0);
    STS_SLAB_S(0);
    __syncthreads();

    for (int s = 0; s < 4; s++) {
        const int b = s & 1;
        if (s + 1 < 4) LDG_SLAB_S(s + 1);

        const uint32_t pA[3] = { sb + plane(b,0), sb + plane(b,1), sb + plane(b,0) };
        const uint32_t pB[3] = { sb + plane(b,2), sb + plane(b,2), sb + plane(b,3) };
#pragma unroll
        for (int ks = 0; ks < 2; ks++) {
            const uint32_t kb = ks * 32;
#pragma unroll
            for (int p = 0; p < 3; p++) {
                uint32_t af[4][4];
#pragma unroll
                for (int mi = 0; mi < 4; mi++)
                    ldsm4(af[mi], pA[p] + aRow + (uint32_t)(mi * 16) * 80u + kb);
                uint32_t bf4[2][4];
#pragma unroll
                for (int nb = 0; nb < 2; nb++)
                    ldsm4(bf4[nb], pB[p] + bRow + (uint32_t)(nb * 16) * 80u + kb);
#pragma unroll
                for (int mi = 0; mi < 4; mi++)
#pragma unroll
                    for (int ni = 0; ni < 4; ni++)
                        mma16816(acc[mi][ni], af[mi],
                                 bf4[ni >> 1][(ni & 1) * 2],
                                 bf4[ni >> 1][(ni & 1) * 2 + 1]);
            }
        }

        if (s + 1 < 4) {
            __syncthreads();
            STS_SLAB_S(b ^ 1);
            __syncthreads();
        }
    }

    // Epilogue: scalar stores (S row stride 2049 is odd -> no float2)
    float* sbase0 = S + (size_t)h * T * T;
    const int rbase = m0 + wm * 64 + (lane >> 2);
    const int cbase = n0 + wn * 32 + (lane & 3) * 2;
#pragma unroll
    for (int mi = 0; mi < 4; mi++) {
#pragma unroll
        for (int half = 0; half < 2; half++) {
            const int t = rbase + mi * 16 + half * 8;
            if (t >= T) continue;
            float* rowp = sbase0 + (size_t)t * T;
#pragma unroll
            for (int ni = 0; ni < 4; ni++) {
                const int sc = cbase + ni * 8;
                if (sc < T)     rowp[sc]     = acc[mi][ni][half * 2 + 0] * 0.125f;
                if (sc + 1 < T) rowp[sc + 1] = acc[mi][ni][half * 2 + 1] * 0.125f;
            }
        }
    }
#undef LDG_SLAB_S
#undef STS_SLAB_S
}

// ===========================================================================
// Row softmax over s in [0, t], register-resident (<=9 values/thread):
// single global read, max, exp, sum, single write. Zero-fills (t, 128-bound).
// ===========================================================================
__global__ __launch_bounds__(256)
void softmax_kernel(float* __restrict__ S) {
    const int T = T_SEQ;
    const int t = blockIdx.x;
    const int h = blockIdx.y;
    float* r = S + ((size_t)h * T + t) * T;
    const int tid = threadIdx.x;
    __shared__ float red[8];
    const int cnt = t + 1;

    float v[9];
    float m = -1e30f;
#pragma unroll
    for (int i = 0; i < 9; i++) {
        int s = tid + i * 256;
        v[i] = (s < cnt) ? r[s] : -1e30f;
        m = fmaxf(m, v[i]);
    }
#pragma unroll
    for (int o = 16; o; o >>= 1) m = fmaxf(m, __shfl_xor_sync(~0u, m, o));
    if ((tid & 31) == 0) red[tid >> 5] = m;
    __syncthreads();
    if (tid < 32) {
        float x = (tid < 8) ? red[tid] : -1e30f;
#pragma unroll
        for (int o = 4; o; o >>= 1) x = fmaxf(x, __shfl_xor_sync(~0u, x, o));
        if (tid == 0) red[0] = x;
    }
    __syncthreads();
    m = red[0];
    __syncthreads();

    float sum = 0.f;
#pragma unroll
    for (int i = 0; i < 9; i++) {
        float e = __expf(v[i] - m);      // invalid lanes: exp(-huge) = 0
        v[i] = e;
        sum += e;
    }
#pragma unroll
    for (int o = 16; o; o >>= 1) sum += __shfl_xor_sync(~0u, sum, o);
    if ((tid & 31) == 0) red[tid >> 5] = sum;
    __syncthreads();
    if (tid < 32) {
        float x = (tid < 8) ? red[tid] : 0.f;
#pragma unroll
        for (int o = 4; o; o >>= 1) x += __shfl_xor_sync(~0u, x, o);
        if (tid == 0) red[0] = x;
    }
    __syncthreads();
    const float inv = 1.0f / red[0];
    const int bound = min((((t >> 7) + 1) << 7), T);
#pragma unroll
    for (int i = 0; i < 9; i++) {
        int s = tid + i * 256;
        if (s < cnt)        r[s] = v[i] * inv;
        else if (s < bound) r[s] = 0.0f;
    }
}

// ===========================================================================
// AV: ctx[t, h*64+d] = sum_{s<=t} P[h,t,s] * vh[h,s,d]   (SIMT, 64x64 tile)
// ===========================================================================
__global__ __launch_bounds__(256)
void av_kernel(const float* __restrict__ S, const float* __restrict__ vh,
               float* __restrict__ ctx) {
    const int T = T_SEQ;
    const int m0 = blockIdx.x * 64;
    const int h  = blockIdx.y;
    const int tid = threadIdx.x;
    const int tx = tid & 15, ty = tid >> 4;

    __shared__ float Ps[16][68];
    __shared__ float Vs[16][68];
    float acc[4][4] = {};

    const float* sbase = S  + (size_t)h * T * T;
    const float* vbase = vh + (size_t)h * T * HDIM;
    const int smax = min(m0 + 63, T - 1);

    const int prow = tid >> 2;
    const int pss  = (tid & 3) * 4;
    const int vsr  = tid >> 4;
    const int vd4  = (tid & 15) * 4;

    for (int s0 = 0; s0 <= smax; s0 += 16) {
        {
            int t = m0 + prow;
#pragma unroll
            for (int i = 0; i < 4; i++) {
                int s = s0 + pss + i;
                float v = 0.f;
                if (t < T && s < T) v = sbase[(size_t)t * T + s];
                Ps[pss + i][prow] = v;
            }
        }
        {
            int s = s0 + vsr;
            float4 vv = make_float4(0.f, 0.f, 0.f, 0.f);
            if (s < T) vv = *(const float4*)(vbase + (size_t)s * HDIM + vd4);
            Vs[vsr][vd4+0] = vv.x; Vs[vsr][vd4+1] = vv.y;
            Vs[vsr][vd4+2] = vv.z; Vs[vsr][vd4+3] = vv.w;
        }
        __syncthreads();
#pragma unroll
        for (int kk = 0; kk < 16; kk++) {
            float4 a4 = *(const float4*)&Ps[kk][ty * 4];
            float4 b4 = *(const float4*)&Vs[kk][tx * 4];
            float a[4] = {a4.x, a4.y, a4.z, a4.w};
            float b[4] = {b4.x, b4.y, b4.z, b4.w};
#pragma unroll
            for (int i = 0; i < 4; i++)
#pragma unroll
                for (int j = 0; j < 4; j++)
                    acc[i][j] = fmaf(a[i], b[j], acc[i][j]);
        }
        __syncthreads();
    }

#pragma unroll
    for (int i = 0; i < 4; i++) {
        int t = m0 + ty * 4 + i;
        if (t >= T) continue;
#pragma unroll
        for (int j = 0; j < 4; j++) {
            int d = tx * 4 + j;
            ctx[(size_t)t * D_MODEL + h * HDIM + d] = acc[i][j];
        }
    }
}

// ===========================================================================
// Launch. Inputs: q,k,v,mask,Wq_w,Wq_b,Wk_w,Wk_b,Wv_w,Wv_b,Er,Wo_w,Wo_b.
// ===========================================================================
extern "C" void kernel_launch(void* const* d_in, const int* in_sizes, int n_in,
                              void* d_out, int out_size) {
    const float* q    = (const float*)d_in[0];
    const float* k    = (const float*)d_in[1];
    const float* v    = (const float*)d_in[2];
    const float* Wq_w = (const float*)d_in[4];
    const float* Wq_b = (const float*)d_in[5];
    const float* Wk_w = (const float*)d_in[6];
    const float* Wk_b = (const float*)d_in[7];
    const float* Wv_w = (const float*)d_in[8];
    const float* Wv_b = (const float*)d_in[9];
    const float* Er   = (const float*)d_in[10];
    const float* Wo_w = (const float*)d_in[11];
    const float* Wo_b = (const float*)d_in[12];
    float* out = (float*)d_out;

    float *qh, *kh, *vh, *S, *ctx;
    cudaGetSymbolAddress((void**)&qh,  g_qh);
    cudaGetSymbolAddress((void**)&kh,  g_kh);
    cudaGetSymbolAddress((void**)&vh,  g_vh);
    cudaGetSymbolAddress((void**)&S,   g_S);
    cudaGetSymbolAddress((void**)&ctx, g_ctx);

    cudaFuncSetAttribute(gemm_mma<1>, cudaFuncAttributeMaxDynamicSharedMemorySize, MMA_SMEM);
    cudaFuncSetAttribute(gemm_mma<0>, cudaFuncAttributeMaxDynamicSharedMemorySize, MMA_SMEM);
    cudaFuncSetAttribute(scores_mma,  cudaFuncAttributeMaxDynamicSharedMemorySize, MMA_SMEM);

    const int mt = (T_SEQ + 127) / 128;          // 17
    dim3 gG(D_MODEL / 128, mt);                  // (8, 17)

    gemm_mma<1><<<gG, 256, MMA_SMEM>>>(q, Wq_w, Wq_b, qh);
    gemm_mma<1><<<gG, 256, MMA_SMEM>>>(k, Wk_w, Wk_b, kh);
    gemm_mma<1><<<gG, 256, MMA_SMEM>>>(v, Wv_w, Wv_b, vh);

    dim3 gS(mt, mt, NHEAD);                      // (17, 17, 16)
    scores_mma<<<gS, 256, MMA_SMEM>>>(qh, kh, Er, S);

    dim3 gSm(T_SEQ, NHEAD);
    softmax_kernel<<<gSm, 256>>>(S);

    dim3 gAV((T_SEQ + 63) / 64, NHEAD);          // (33, 16)
    av_kernel<<<gAV, 256>>>(S, vh, ctx);

    gemm_mma<0><<<gG, 256, MMA_SMEM>>>(ctx, Wo_w, Wo_b, out);
}